// round 14
// baseline (speedup 1.0000x reference)
#include <cuda_runtime.h>
#include <cuda_bf16.h>
#include <cstdint>

#define NN 200000
#define NE 600000
#define NG 10000
#define FIN 32
#define HD 128
#define BN_EPS 1e-5f
#define NBLK 1563   // ceil(200000/128)

// smem layout (bytes). Group Z tiles: 64 rows * 272 B * 2 planes = 34816 per group.
#define GZ   17408            // one 64x272 plane
#define OFF_ZG0 2048
#define OFF_ZG1 (OFF_ZG0 + 2 * GZ)        // 36864
#define OFF_W1H (OFF_ZG1 + 2 * GZ)        // 71680
#define OFF_W1L (OFF_W1H + 2 * GZ)        // 106496
#define OFF_W2H (OFF_W1L + 2 * GZ)        // 141312
#define OFF_W2L (OFF_W2H + 2 * GZ)        // 176128
#define SMEM_TOTAL (OFF_W2L + 2 * GZ)     // 210944 B

// ---------------- scratch (no allocations allowed) ----------------
__device__ float g_scr_a[NN * FIN];
__device__ float g_h1[NN * HD];
__device__ float g_scr_b[NN * HD];
__device__ float g_h2[NN * HD];
__device__ float g_scr_c[NN * HD];
__device__ float g_hg[NG * HD];

// W^T bf16 planes [hi=0/lo=1][n*K + k] — 16B-aligned (cp.async.cg src requirement)
__device__ __align__(16) __nv_bfloat16 g_W1a[2][128 * 32];
__device__ __align__(16) __nv_bfloat16 g_W2a[2][128 * 128];
__device__ __align__(16) __nv_bfloat16 g_W1b[2][128 * 128];
__device__ __align__(16) __nv_bfloat16 g_W2b[2][128 * 128];
__device__ __align__(16) __nv_bfloat16 g_W1c[2][128 * 128];
__device__ __align__(16) __nv_bfloat16 g_W2c[2][128 * 128];

// ---------------- helpers ----------------
__device__ __forceinline__ uint32_t smem_u32(const void* p) {
    uint32_t a;
    asm("{ .reg .u64 t; cvta.to.shared.u64 t, %1; cvt.u32.u64 %0, t; }" : "=r"(a) : "l"(p));
    return a;
}
__device__ __forceinline__ void ldsm4(uint32_t* r, uint32_t a) {
    asm volatile("ldmatrix.sync.aligned.m8n8.x4.shared.b16 {%0,%1,%2,%3}, [%4];"
                 : "=r"(r[0]), "=r"(r[1]), "=r"(r[2]), "=r"(r[3]) : "r"(a));
}
__device__ __forceinline__ void mma16816(float* c, const uint32_t* a, uint32_t b0, uint32_t b1) {
    asm volatile("mma.sync.aligned.m16n8k16.row.col.f32.bf16.bf16.f32 "
                 "{%0,%1,%2,%3}, {%4,%5,%6,%7}, {%8,%9}, {%0,%1,%2,%3};"
                 : "+f"(c[0]), "+f"(c[1]), "+f"(c[2]), "+f"(c[3])
                 : "r"(a[0]), "r"(a[1]), "r"(a[2]), "r"(a[3]), "r"(b0), "r"(b1));
}
#define CP16(dst, src) \
    asm volatile("cp.async.cg.shared.global [%0], [%1], 16;" :: "r"(dst), "l"(src) : "memory")
#define CP_COMMIT() asm volatile("cp.async.commit_group;" ::: "memory")
#define CP_WAIT0()  asm volatile("cp.async.wait_group 0;" ::: "memory")
// group barrier: id 1 for G0, 2 for G1, 256 threads each
#define BARG(g) asm volatile("bar.sync %0, 256;" :: "r"((g) + 1) : "memory")

__device__ __forceinline__ uint32_t pack_bf2(float a, float b) {
    __nv_bfloat162 t = __floats2bfloat162_rn(a, b);
    return *reinterpret_cast<uint32_t*>(&t);
}
__device__ __forceinline__ float bf_hi(float f) {
    return __bfloat162float(__float2bfloat16(f));
}

// ---------------- init: copy x -> scr_a, zero hg ----------------
__global__ void init_kernel(const float* __restrict__ x) {
    int i = blockIdx.x * blockDim.x + threadIdx.x;
    const int ncopy = NN * FIN / 4;
    const int nzero = NG * HD / 4;
    if (i < ncopy) {
        ((float4*)g_scr_a)[i] = ((const float4*)x)[i];
    } else {
        int j = i - ncopy;
        if (j < nzero) ((float4*)g_hg)[j] = make_float4(0.f, 0.f, 0.f, 0.f);
    }
}

// ---------------- weight -> W^T bf16 hi/lo planes ----------------
__global__ void setup_kernel(const float* __restrict__ W1a, const float* __restrict__ W2a,
                             const float* __restrict__ W1b, const float* __restrict__ W2b,
                             const float* __restrict__ W1c, const float* __restrict__ W2c) {
    int b = blockIdx.x;
    int tid = threadIdx.x;
    const float* W;
    __nv_bfloat16 *th, *tl;
    int K;
    switch (b) {
        case 0: W = W1a; th = g_W1a[0]; tl = g_W1a[1]; K = 32;  break;
        case 1: W = W2a; th = g_W2a[0]; tl = g_W2a[1]; K = 128; break;
        case 2: W = W1b; th = g_W1b[0]; tl = g_W1b[1]; K = 128; break;
        case 3: W = W2b; th = g_W2b[0]; tl = g_W2b[1]; K = 128; break;
        case 4: W = W1c; th = g_W1c[0]; tl = g_W1c[1]; K = 128; break;
        default: W = W2c; th = g_W2c[0]; tl = g_W2c[1]; K = 128; break;
    }
    int nel = K * 128;
    for (int i = tid; i < nel; i += 256) {
        int k = i >> 7, n = i & 127;   // W[k][n] row-major
        float w = W[i];
        float hi = bf_hi(w);
        th[n * K + k] = __float2bfloat16(w);
        tl[n * K + k] = __float2bfloat16(w - hi);
    }
}

// ---------------- scatter-add ----------------
template <int DIM>
__global__ void scatter_kernel(const int* __restrict__ ei,
                               const float* __restrict__ h,
                               float* __restrict__ scr) {
    const int CH = DIM / 4;
    long long id = (long long)blockIdx.x * blockDim.x + threadIdx.x;
    int e = (int)(id / CH);
    int c = (int)(id % CH);
    if (e >= NE) return;
    int src = __ldg(&ei[e]);
    int dst = __ldg(&ei[NE + e]);
    float4 v = __ldg(((const float4*)(h + (size_t)src * DIM)) + c);
    atomicAdd(((float4*)(scr + (size_t)dst * DIM)) + c, v);
}

// ---------------- mma phase on a 64-row group tile ----------------
// acc += Zhi@Whi + Zhi@Wlo + Zlo@Whi
template <int KS>
__device__ __forceinline__ void do_phase(uint32_t sb, uint32_t zoff,
                                         int wrow, int whalf, int lane,
                                         uint32_t WHo, uint32_t WLo, float acc[8][4]) {
#pragma unroll
    for (int ks = 0; ks < KS; ks++) {
        uint32_t arow = wrow + (lane & 15);
        uint32_t acol = ks * 16 + ((lane >> 4) << 3);
        uint32_t ah[4], al[4];
        ldsm4(ah, sb + zoff + arow * 272 + acol * 2);
        ldsm4(al, sb + zoff + GZ + arow * 272 + acol * 2);
#pragma unroll
        for (int tp = 0; tp < 4; tp++) {
            int n0 = whalf * 64 + tp * 16;
            uint32_t brow = n0 + ((lane >> 4) << 3) + (lane & 7);
            uint32_t bcol = ks * 16 + (((lane >> 3) & 1) << 3);
            uint32_t bh[4], bl[4];
            ldsm4(bh, sb + WHo + brow * 272 + bcol * 2);
            ldsm4(bl, sb + WLo + brow * 272 + bcol * 2);
            mma16816(acc[2 * tp],     ah, bh[0], bh[1]);
            mma16816(acc[2 * tp + 1], ah, bh[2], bh[3]);
            mma16816(acc[2 * tp],     ah, bl[0], bl[1]);
            mma16816(acc[2 * tp + 1], ah, bl[2], bl[3]);
            mma16816(acc[2 * tp],     al, bh[0], bh[1]);
            mma16816(acc[2 * tp + 1], al, bh[2], bh[3]);
        }
    }
}

// ---------------- fused GIN layer, two independent warp-groups ----------------
// K1 = 32 or 128. MODE 0: write h_next+scr_next. MODE 1: pool into g_hg.
template <int K1, int MODE>
__global__ void __launch_bounds__(512, 1)
gin_mma_kernel(const float* __restrict__ in,
               const __nv_bfloat16* __restrict__ W1h, const __nv_bfloat16* __restrict__ W1l,
               const __nv_bfloat16* __restrict__ W2h, const __nv_bfloat16* __restrict__ W2l,
               const float* __restrict__ b1, const float* __restrict__ gg,
               const float* __restrict__ be, const float* __restrict__ rm,
               const float* __restrict__ rv, const float* __restrict__ b2,
               float* __restrict__ h_next, float* __restrict__ scr_next,
               const int* __restrict__ batch) {
    extern __shared__ char smem[];
    float* smul = (float*)(smem);
    float* sadd = (float*)(smem + 512);
    float* sb2  = (float*)(smem + 1024);
    uint32_t sb = smem_u32(smem);

    int tid = threadIdx.x, lane = tid & 31, wid = tid >> 5;
    int grp = tid >> 8;            // 0 / 1
    int lt = tid & 255;            // thread within group
    int lw = wid & 7;              // warp within group
    int wrow = (lw & 3) * 16;      // row base within 64-row group tile
    int whalf = lw >> 2;           // n-half 0/1
    uint32_t zoff = grp ? OFF_ZG1 : OFF_ZG0;
    int base = blockIdx.x * 128 + grp * 64;   // group's first node

    // BN params
    if (tid < 128) {
        float mul = gg[tid] * rsqrtf(rv[tid] + BN_EPS);
        smul[tid] = mul;
        sadd[tid] = (b1[tid] - rm[tid]) * mul + be[tid];
        sb2[tid] = b2[tid];
    }

    // ---- async weight staging (whole block cooperates) ----
    const int C1 = K1 / 8;   // 16B chunks per W1 row
    for (int i = tid; i < 128 * C1; i += 512) {
        int n = i / C1, j = i % C1;
        CP16(sb + OFF_W1H + n * 272 + j * 16, (const char*)W1h + n * K1 * 2 + j * 16);
        CP16(sb + OFF_W1L + n * 272 + j * 16, (const char*)W1l + n * K1 * 2 + j * 16);
    }
    for (int i = tid; i < 128 * 16; i += 512) {
        int n = i >> 4, j = i & 15;
        CP16(sb + OFF_W2H + n * 272 + j * 16, (const char*)W2h + n * 256 + j * 16);
        CP16(sb + OFF_W2L + n * 272 + j * 16, (const char*)W2l + n * 256 + j * 16);
    }
    CP_COMMIT();

    // ---- stage A (own 64 rows) into group Z as bf16 hi/lo ----
    {
        int row = lt >> 2, q = lt & 3;       // row 0-63, quarter
        long long node = base + row;
        bool valid = node < NN;
        if (K1 == 128) {
            const float4* src = (const float4*)(in + node * 128 + q * 32);
#pragma unroll
            for (int j = 0; j < 8; j++) {
                float4 v = valid ? __ldg(src + j) : make_float4(0.f, 0.f, 0.f, 0.f);
                int col = q * 32 + j * 4;
                float h0 = bf_hi(v.x), h1 = bf_hi(v.y), h2 = bf_hi(v.z), h3 = bf_hi(v.w);
                *(uint32_t*)(smem + zoff + row * 272 + col * 2)          = pack_bf2(v.x, v.y);
                *(uint32_t*)(smem + zoff + row * 272 + col * 2 + 4)      = pack_bf2(v.z, v.w);
                *(uint32_t*)(smem + zoff + GZ + row * 272 + col * 2)     = pack_bf2(v.x - h0, v.y - h1);
                *(uint32_t*)(smem + zoff + GZ + row * 272 + col * 2 + 4) = pack_bf2(v.z - h2, v.w - h3);
            }
        } else {
            const float4* src = (const float4*)(in + node * 32 + q * 8);
#pragma unroll
            for (int j = 0; j < 2; j++) {
                float4 v = valid ? __ldg(src + j) : make_float4(0.f, 0.f, 0.f, 0.f);
                int col = q * 8 + j * 4;
                float h0 = bf_hi(v.x), h1 = bf_hi(v.y), h2 = bf_hi(v.z), h3 = bf_hi(v.w);
                *(uint32_t*)(smem + zoff + row * 272 + col * 2)          = pack_bf2(v.x, v.y);
                *(uint32_t*)(smem + zoff + row * 272 + col * 2 + 4)      = pack_bf2(v.z, v.w);
                *(uint32_t*)(smem + zoff + GZ + row * 272 + col * 2)     = pack_bf2(v.x - h0, v.y - h1);
                *(uint32_t*)(smem + zoff + GZ + row * 272 + col * 2 + 4) = pack_bf2(v.z - h2, v.w - h3);
            }
        }
    }
    CP_WAIT0();
    __syncthreads();     // weights + both A tiles + BN params visible; groups diverge after

    // ---- phase 1 ----
    float acc[8][4];
#pragma unroll
    for (int t = 0; t < 8; t++)
#pragma unroll
        for (int j = 0; j < 4; j++) acc[t][j] = 0.f;
    do_phase<K1 / 16>(sb, zoff, wrow, whalf, lane, OFF_W1H, OFF_W1L, acc);
    BARG(grp);           // group done reading its Z

    // ---- epilogue 1: BN + ReLU -> group Z (in place) ----
#pragma unroll
    for (int t = 0; t < 8; t++) {
        int col = whalf * 64 + 8 * t + 2 * (lane & 3);
        float m0 = smul[col], m1 = smul[col + 1];
        float a0 = sadd[col], a1 = sadd[col + 1];
        int r0 = wrow + (lane >> 2), r1 = r0 + 8;
        float f0 = fmaxf(fmaf(acc[t][0], m0, a0), 0.f);
        float f1 = fmaxf(fmaf(acc[t][1], m1, a1), 0.f);
        float f2 = fmaxf(fmaf(acc[t][2], m0, a0), 0.f);
        float f3 = fmaxf(fmaf(acc[t][3], m1, a1), 0.f);
        float h0 = bf_hi(f0), h1 = bf_hi(f1), h2 = bf_hi(f2), h3 = bf_hi(f3);
        *(uint32_t*)(smem + zoff + r0 * 272 + col * 2)      = pack_bf2(f0, f1);
        *(uint32_t*)(smem + zoff + GZ + r0 * 272 + col * 2) = pack_bf2(f0 - h0, f1 - h1);
        *(uint32_t*)(smem + zoff + r1 * 272 + col * 2)      = pack_bf2(f2, f3);
        *(uint32_t*)(smem + zoff + GZ + r1 * 272 + col * 2) = pack_bf2(f2 - h2, f3 - h3);
    }
    BARG(grp);

    // ---- phase 2 ----
#pragma unroll
    for (int t = 0; t < 8; t++)
#pragma unroll
        for (int j = 0; j < 4; j++) acc[t][j] = 0.f;
    do_phase<8>(sb, zoff, wrow, whalf, lane, OFF_W2H, OFF_W2L, acc);
    BARG(grp);           // group done reading Z; reuse for fp32 staging

    // ---- epilogue 2: bias + ReLU -> fp32 staging (528 B row stride) ----
#pragma unroll
    for (int t = 0; t < 8; t++) {
        int col = whalf * 64 + 8 * t + 2 * (lane & 3);
        float bb0 = sb2[col], bb1 = sb2[col + 1];
        int r0 = wrow + (lane >> 2), r1 = r0 + 8;
        float2 v0 = make_float2(fmaxf(acc[t][0] + bb0, 0.f), fmaxf(acc[t][1] + bb1, 0.f));
        float2 v1 = make_float2(fmaxf(acc[t][2] + bb0, 0.f), fmaxf(acc[t][3] + bb1, 0.f));
        *(float2*)(smem + zoff + r0 * 528 + col * 4) = v0;
        *(float2*)(smem + zoff + r1 * 528 + col * 4) = v1;
    }
    BARG(grp);

    // ---- global write: coalesced (MODE 0) / pooled atomics (MODE 1) ----
    {
        int c4 = lt & 31;         // 16B chunk = cols 4c4..4c4+3
        int rg = (lt >> 5) * 8;   // 8 rows per thread (0..63)
        if (MODE == 0) {
#pragma unroll
            for (int rr = 0; rr < 8; rr++) {
                int row = rg + rr;
                long long node = base + row;
                if (node < NN) {
                    float4 v = *(float4*)(smem + zoff + row * 528 + c4 * 16);
                    *(float4*)(h_next + node * 128 + c4 * 4) = v;
                    *(float4*)(scr_next + node * 128 + c4 * 4) = v;
                }
            }
        } else {
            int prev = -1;
            float4 sum = make_float4(0.f, 0.f, 0.f, 0.f);
#pragma unroll
            for (int rr = 0; rr < 8; rr++) {
                int row = rg + rr;
                long long node = base + row;
                if (node >= NN) break;
                float4 v = *(float4*)(smem + zoff + row * 528 + c4 * 16);
                int bg = __ldg(&batch[node]);
                if (bg == prev) {
                    sum.x += v.x; sum.y += v.y; sum.z += v.z; sum.w += v.w;
                } else {
                    if (prev >= 0)
                        atomicAdd((float4*)(g_hg + (size_t)prev * 128 + c4 * 4), sum);
                    prev = bg;
                    sum = v;
                }
            }
            if (prev >= 0)
                atomicAdd((float4*)(g_hg + (size_t)prev * 128 + c4 * 4), sum);
        }
    }
}

// ---------------- pooled MLP head ----------------
__global__ void pool_head_kernel(const float* __restrict__ lw1,
                                 const float* __restrict__ lb1,
                                 const float* __restrict__ lw2,
                                 const float* __restrict__ lb2,
                                 float* __restrict__ out) {
    extern __shared__ float psm[];
    float* Ws   = psm;
    float* hrow = psm + HD * HD;
    float* redb = hrow + HD;

    int t = threadIdx.x;
    for (int i = t; i < HD * HD / 4; i += 128)
        ((float4*)Ws)[i] = __ldg(((const float4*)lw1) + i);
    float lb1t = __ldg(&lb1[t]);
    float w2t  = __ldg(&lw2[t]);
    float lb2v = __ldg(&lb2[0]);
    __syncthreads();

    int gbase = blockIdx.x * 8;
    for (int gi = 0; gi < 8; gi++) {
        int g = gbase + gi;
        hrow[t] = g_hg[(size_t)g * HD + t];
        __syncthreads();
        float a = 0.f;
#pragma unroll
        for (int k = 0; k < HD; k++)
            a = fmaf(hrow[k], Ws[k * HD + t], a);
        float p = fmaxf(a + lb1t, 0.f) * w2t;
#pragma unroll
        for (int o = 16; o > 0; o >>= 1)
            p += __shfl_xor_sync(0xffffffffu, p, o);
        if ((t & 31) == 0) redb[t >> 5] = p;
        __syncthreads();
        if (t == 0)
            out[g] = redb[0] + redb[1] + redb[2] + redb[3] + lb2v;
        __syncthreads();
    }
}

// ---------------- launch ----------------
extern "C" void kernel_launch(void* const* d_in, const int* in_sizes, int n_in,
                              void* d_out, int out_size) {
    const float* x   = (const float*)d_in[0];
    const int* ei    = (const int*)d_in[1];
    const int* batch = (const int*)d_in[2];
    const float* W1a = (const float*)d_in[3];
    const float* b1a = (const float*)d_in[4];
    const float* ga  = (const float*)d_in[5];
    const float* bea = (const float*)d_in[6];
    const float* rma = (const float*)d_in[7];
    const float* rva = (const float*)d_in[8];
    const float* W2a = (const float*)d_in[9];
    const float* b2a = (const float*)d_in[10];
    const float* W1b = (const float*)d_in[11];
    const float* b1b = (const float*)d_in[12];
    const float* gb  = (const float*)d_in[13];
    const float* beb = (const float*)d_in[14];
    const float* rmb = (const float*)d_in[15];
    const float* rvb = (const float*)d_in[16];
    const float* W2b = (const float*)d_in[17];
    const float* b2b = (const float*)d_in[18];
    const float* W1c = (const float*)d_in[19];
    const float* b1c = (const float*)d_in[20];
    const float* gc  = (const float*)d_in[21];
    const float* bec = (const float*)d_in[22];
    const float* rmc = (const float*)d_in[23];
    const float* rvc = (const float*)d_in[24];
    const float* W2c = (const float*)d_in[25];
    const float* b2c = (const float*)d_in[26];
    const float* lw1 = (const float*)d_in[27];
    const float* lb1 = (const float*)d_in[28];
    const float* lw2 = (const float*)d_in[29];
    const float* lb2 = (const float*)d_in[30];
    float* out = (float*)d_out;

    float *scr_a, *h1, *scr_b, *h2, *scr_c;
    cudaGetSymbolAddress((void**)&scr_a, g_scr_a);
    cudaGetSymbolAddress((void**)&h1,    g_h1);
    cudaGetSymbolAddress((void**)&scr_b, g_scr_b);
    cudaGetSymbolAddress((void**)&h2,    g_h2);
    cudaGetSymbolAddress((void**)&scr_c, g_scr_c);

    __nv_bfloat16 *Wa1, *Wa2, *Wb1, *Wb2, *Wc1, *Wc2;
    cudaGetSymbolAddress((void**)&Wa1, g_W1a);
    cudaGetSymbolAddress((void**)&Wa2, g_W2a);
    cudaGetSymbolAddress((void**)&Wb1, g_W1b);
    cudaGetSymbolAddress((void**)&Wb2, g_W2b);
    cudaGetSymbolAddress((void**)&Wc1, g_W1c);
    cudaGetSymbolAddress((void**)&Wc2, g_W2c);

    const int smem_p = (HD * HD + HD + 4) * 4;

    cudaFuncSetAttribute(gin_mma_kernel<32, 0>,
                         cudaFuncAttributeMaxDynamicSharedMemorySize, SMEM_TOTAL);
    cudaFuncSetAttribute(gin_mma_kernel<128, 0>,
                         cudaFuncAttributeMaxDynamicSharedMemorySize, SMEM_TOTAL);
    cudaFuncSetAttribute(gin_mma_kernel<128, 1>,
                         cudaFuncAttributeMaxDynamicSharedMemorySize, SMEM_TOTAL);
    cudaFuncSetAttribute(pool_head_kernel,
                         cudaFuncAttributeMaxDynamicSharedMemorySize, smem_p);

    // 1. init + weight conversion
    init_kernel<<<7500, 256>>>(x);
    setup_kernel<<<6, 256>>>(W1a, W2a, W1b, W2b, W1c, W2c);

    // 2. scatter x into scr_a
    scatter_kernel<FIN><<<18750, 256>>>(ei, x, scr_a);

    // 3. layer a
    gin_mma_kernel<32, 0><<<NBLK, 512, SMEM_TOTAL>>>(
        scr_a, Wa1, Wa1 + 128 * 32, Wa2, Wa2 + 128 * 128,
        b1a, ga, bea, rma, rva, b2a, h1, scr_b, nullptr);

    // 4. scatter h1 into scr_b
    scatter_kernel<HD><<<75000, 256>>>(ei, h1, scr_b);

    // 5. layer b
    gin_mma_kernel<128, 0><<<NBLK, 512, SMEM_TOTAL>>>(
        scr_b, Wb1, Wb1 + 128 * 128, Wb2, Wb2 + 128 * 128,
        b1b, gb, beb, rmb, rvb, b2b, h2, scr_c, nullptr);

    // 6. scatter h2 into scr_c
    scatter_kernel<HD><<<75000, 256>>>(ei, h2, scr_c);

    // 7. layer c + fused pool
    gin_mma_kernel<128, 1><<<NBLK, 512, SMEM_TOTAL>>>(
        scr_c, Wc1, Wc1 + 128 * 128, Wc2, Wc2 + 128 * 128,
        b1c, gc, bec, rmc, rvc, b2c, nullptr, nullptr, batch);

    // 8. head MLP
    pool_head_kernel<<<NG / 8, 128, smem_p>>>(lw1, lb1, lw2, lb2, out);
}

// round 15
// speedup vs baseline: 1.0157x; 1.0157x over previous
#include <cuda_runtime.h>
#include <cuda_bf16.h>
#include <cstdint>

#define NN 200000
#define NE 600000
#define NG 10000
#define FIN 32
#define HD 128
#define BN_EPS 1e-5f
#define GRID 148
#define TIL 3125            // 200000 / 64 exact

// smem layout (bytes). Z buffers: 64 rows * 272 B, hi+lo planes.
#define GZ 17408            // one 64x272 plane
#define ZBUF 34816          // hi+lo
#define OFF_Z0 2048
#define OFF_Z1 (OFF_Z0 + ZBUF)            // 36864
#define OFF_W1H (OFF_Z1 + ZBUF)           // 71680
#define OFF_W1L (OFF_W1H + ZBUF)          // 106496
#define OFF_W2H (OFF_W1L + ZBUF)          // 141312
#define OFF_W2L (OFF_W2H + ZBUF)          // 176128
#define SMEM_TOTAL (OFF_W2L + ZBUF)       // 210944 B

// ---------------- scratch ----------------
__device__ float g_scr_a[NN * FIN];
__device__ float g_h1[NN * HD];
__device__ float g_scr_b[NN * HD];
__device__ float g_h2[NN * HD];
__device__ float g_scr_c[NN * HD];
__device__ float g_hg[NG * HD];

// W^T bf16 planes [hi=0/lo=1][n*K + k] — 16B-aligned (cp.async src)
__device__ __align__(16) __nv_bfloat16 g_W1a[2][128 * 32];
__device__ __align__(16) __nv_bfloat16 g_W2a[2][128 * 128];
__device__ __align__(16) __nv_bfloat16 g_W1b[2][128 * 128];
__device__ __align__(16) __nv_bfloat16 g_W2b[2][128 * 128];
__device__ __align__(16) __nv_bfloat16 g_W1c[2][128 * 128];
__device__ __align__(16) __nv_bfloat16 g_W2c[2][128 * 128];

// ---------------- helpers ----------------
__device__ __forceinline__ uint32_t smem_u32(const void* p) {
    uint32_t a;
    asm("{ .reg .u64 t; cvta.to.shared.u64 t, %1; cvt.u32.u64 %0, t; }" : "=r"(a) : "l"(p));
    return a;
}
__device__ __forceinline__ void ldsm4(uint32_t* r, uint32_t a) {
    asm volatile("ldmatrix.sync.aligned.m8n8.x4.shared.b16 {%0,%1,%2,%3}, [%4];"
                 : "=r"(r[0]), "=r"(r[1]), "=r"(r[2]), "=r"(r[3]) : "r"(a));
}
__device__ __forceinline__ void mma16816(float* c, const uint32_t* a, uint32_t b0, uint32_t b1) {
    asm volatile("mma.sync.aligned.m16n8k16.row.col.f32.bf16.bf16.f32 "
                 "{%0,%1,%2,%3}, {%4,%5,%6,%7}, {%8,%9}, {%0,%1,%2,%3};"
                 : "+f"(c[0]), "+f"(c[1]), "+f"(c[2]), "+f"(c[3])
                 : "r"(a[0]), "r"(a[1]), "r"(a[2]), "r"(a[3]), "r"(b0), "r"(b1));
}
#define CP16(dst, src) \
    asm volatile("cp.async.cg.shared.global [%0], [%1], 16;" :: "r"(dst), "l"(src) : "memory")
#define CP_COMMIT() asm volatile("cp.async.commit_group;" ::: "memory")
#define CP_WAIT0()  asm volatile("cp.async.wait_group 0;" ::: "memory")

__device__ __forceinline__ uint32_t pack_bf2(float a, float b) {
    __nv_bfloat162 t = __floats2bfloat162_rn(a, b);
    return *reinterpret_cast<uint32_t*>(&t);
}
__device__ __forceinline__ float bf_hi(float f) {
    return __bfloat162float(__float2bfloat16(f));
}

// ---------------- init ----------------
__global__ void init_kernel(const float* __restrict__ x) {
    int i = blockIdx.x * blockDim.x + threadIdx.x;
    const int ncopy = NN * FIN / 4;
    const int nzero = NG * HD / 4;
    if (i < ncopy) {
        ((float4*)g_scr_a)[i] = ((const float4*)x)[i];
    } else {
        int j = i - ncopy;
        if (j < nzero) ((float4*)g_hg)[j] = make_float4(0.f, 0.f, 0.f, 0.f);
    }
}

// ---------------- weight -> W^T bf16 hi/lo planes ----------------
__global__ void setup_kernel(const float* __restrict__ W1a, const float* __restrict__ W2a,
                             const float* __restrict__ W1b, const float* __restrict__ W2b,
                             const float* __restrict__ W1c, const float* __restrict__ W2c) {
    int b = blockIdx.x;
    int tid = threadIdx.x;
    const float* W;
    __nv_bfloat16 *th, *tl;
    int K;
    switch (b) {
        case 0: W = W1a; th = g_W1a[0]; tl = g_W1a[1]; K = 32;  break;
        case 1: W = W2a; th = g_W2a[0]; tl = g_W2a[1]; K = 128; break;
        case 2: W = W1b; th = g_W1b[0]; tl = g_W1b[1]; K = 128; break;
        case 3: W = W2b; th = g_W2b[0]; tl = g_W2b[1]; K = 128; break;
        case 4: W = W1c; th = g_W1c[0]; tl = g_W1c[1]; K = 128; break;
        default: W = W2c; th = g_W2c[0]; tl = g_W2c[1]; K = 128; break;
    }
    int nel = K * 128;
    for (int i = tid; i < nel; i += 256) {
        int k = i >> 7, n = i & 127;   // W[k][n] row-major
        float w = W[i];
        float hi = bf_hi(w);
        th[n * K + k] = __float2bfloat16(w);
        tl[n * K + k] = __float2bfloat16(w - hi);
    }
}

// ---------------- scatter-add ----------------
template <int DIM>
__global__ void scatter_kernel(const int* __restrict__ ei,
                               const float* __restrict__ h,
                               float* __restrict__ scr) {
    const int CH = DIM / 4;
    long long id = (long long)blockIdx.x * blockDim.x + threadIdx.x;
    int e = (int)(id / CH);
    int c = (int)(id % CH);
    if (e >= NE) return;
    int src = __ldg(&ei[e]);
    int dst = __ldg(&ei[NE + e]);
    float4 v = __ldg(((const float4*)(h + (size_t)src * DIM)) + c);
    atomicAdd(((float4*)(scr + (size_t)dst * DIM)) + c, v);
}

// ---------------- mma phase on a 64-row tile ----------------
// acc += Zhi@Whi + Zhi@Wlo + Zlo@Whi
template <int KS>
__device__ __forceinline__ void do_phase(uint32_t sb, uint32_t zoff,
                                         int wrow, int whalf, int lane,
                                         uint32_t WHo, uint32_t WLo, float acc[8][4]) {
#pragma unroll
    for (int ks = 0; ks < KS; ks++) {
        uint32_t arow = wrow + (lane & 15);
        uint32_t acol = ks * 16 + ((lane >> 4) << 3);
        uint32_t ah[4], al[4];
        ldsm4(ah, sb + zoff + arow * 272 + acol * 2);
        ldsm4(al, sb + zoff + GZ + arow * 272 + acol * 2);
#pragma unroll
        for (int tp = 0; tp < 4; tp++) {
            int n0 = whalf * 64 + tp * 16;
            uint32_t brow = n0 + ((lane >> 4) << 3) + (lane & 7);
            uint32_t bcol = ks * 16 + (((lane >> 3) & 1) << 3);
            uint32_t bh[4], bl[4];
            ldsm4(bh, sb + WHo + brow * 272 + bcol * 2);
            ldsm4(bl, sb + WLo + brow * 272 + bcol * 2);
            mma16816(acc[2 * tp],     ah, bh[0], bh[1]);
            mma16816(acc[2 * tp + 1], ah, bh[2], bh[3]);
            mma16816(acc[2 * tp],     ah, bl[0], bl[1]);
            mma16816(acc[2 * tp + 1], ah, bl[2], bl[3]);
            mma16816(acc[2 * tp],     al, bh[0], bh[1]);
            mma16816(acc[2 * tp + 1], al, bh[2], bh[3]);
        }
    }
}

// split pre-loaded A regs into a Z buffer (bf16 hi/lo)
template <int NF4>
__device__ __forceinline__ void split_to_z(char* smem, uint32_t zoff, int row, int q,
                                           const float4* pre) {
#pragma unroll
    for (int j = 0; j < NF4; j++) {
        float4 v = pre[j];
        int col = q * (NF4 * 4) + j * 4;
        float h0 = bf_hi(v.x), h1 = bf_hi(v.y), h2 = bf_hi(v.z), h3 = bf_hi(v.w);
        *(uint32_t*)(smem + zoff + row * 272 + col * 2)          = pack_bf2(v.x, v.y);
        *(uint32_t*)(smem + zoff + row * 272 + col * 2 + 4)      = pack_bf2(v.z, v.w);
        *(uint32_t*)(smem + zoff + GZ + row * 272 + col * 2)     = pack_bf2(v.x - h0, v.y - h1);
        *(uint32_t*)(smem + zoff + GZ + row * 272 + col * 2 + 4) = pack_bf2(v.z - h2, v.w - h3);
    }
}

// ---------------- persistent fused GIN layer ----------------
// K1 = 32 or 128. MODE 0: write h_next+scr_next. MODE 1: pool into g_hg.
template <int K1, int MODE>
__global__ void __launch_bounds__(256, 1)
gin_mma_kernel(const float* __restrict__ in,
               const __nv_bfloat16* __restrict__ W1h, const __nv_bfloat16* __restrict__ W1l,
               const __nv_bfloat16* __restrict__ W2h, const __nv_bfloat16* __restrict__ W2l,
               const float* __restrict__ b1, const float* __restrict__ gg,
               const float* __restrict__ be, const float* __restrict__ rm,
               const float* __restrict__ rv, const float* __restrict__ b2,
               float* __restrict__ h_next, float* __restrict__ scr_next,
               const int* __restrict__ batch) {
    extern __shared__ char smem[];
    float* smul = (float*)(smem);
    float* sadd = (float*)(smem + 512);
    float* sb2  = (float*)(smem + 1024);
    uint32_t sb = smem_u32(smem);

    const int NF4 = K1 / 16;            // float4 per thread-quarter (8 or 2)
    int tid = threadIdx.x, lane = tid & 31, wid = tid >> 5;
    int wrow = (wid & 3) * 16;          // warp row base in 64-row tile
    int whalf = wid >> 2;               // n-half 0/1
    int arow = tid >> 2, aq = tid & 3;  // A-staging: row 0-63, quarter

    // BN params
    if (tid < 128) {
        float mul = gg[tid] * rsqrtf(rv[tid] + BN_EPS);
        smul[tid] = mul;
        sadd[tid] = (b1[tid] - rm[tid]) * mul + be[tid];
        sb2[tid] = b2[tid];
    }

    // ---- weights once per block ----
    const int C1 = K1 / 8;
    for (int i = tid; i < 128 * C1; i += 256) {
        int n = i / C1, j = i % C1;
        CP16(sb + OFF_W1H + n * 272 + j * 16, (const char*)W1h + n * K1 * 2 + j * 16);
        CP16(sb + OFF_W1L + n * 272 + j * 16, (const char*)W1l + n * K1 * 2 + j * 16);
    }
    for (int i = tid; i < 128 * 16; i += 256) {
        int n = i >> 4, j = i & 15;
        CP16(sb + OFF_W2H + n * 272 + j * 16, (const char*)W2h + n * 256 + j * 16);
        CP16(sb + OFF_W2L + n * 272 + j * 16, (const char*)W2l + n * 256 + j * 16);
    }
    CP_COMMIT();

    // ---- prime: load tile0 into Z[cur] ----
    int tile = blockIdx.x;
    uint32_t zcur = OFF_Z0, znxt = OFF_Z1;
    {
        float4 pre[8];
        const float4* src = (const float4*)(in + (size_t)(tile * 64 + arow) * K1 + aq * (NF4 * 4));
#pragma unroll
        for (int j = 0; j < NF4; j++) pre[j] = __ldg(src + j);
        split_to_z<NF4>(smem, zcur, arow, aq, pre);
    }
    CP_WAIT0();
    __syncthreads();

    while (tile < TIL) {
        int tn = tile + GRID;
        int base = tile * 64;

        // ---- prefetch next tile's A into registers ----
        float4 pre[8];
        if (tn < TIL) {
            const float4* src = (const float4*)(in + (size_t)(tn * 64 + arow) * K1 + aq * (NF4 * 4));
#pragma unroll
            for (int j = 0; j < NF4; j++) pre[j] = __ldg(src + j);
        }

        // ---- phase 1 ----
        float acc[8][4];
#pragma unroll
        for (int t = 0; t < 8; t++)
#pragma unroll
            for (int j = 0; j < 4; j++) acc[t][j] = 0.f;
        do_phase<K1 / 16>(sb, zcur, wrow, whalf, lane, OFF_W1H, OFF_W1L, acc);
        __syncthreads();

        // ---- epilogue 1: BN + ReLU -> Z[cur] in place ----
#pragma unroll
        for (int t = 0; t < 8; t++) {
            int col = whalf * 64 + 8 * t + 2 * (lane & 3);
            float m0 = smul[col], m1 = smul[col + 1];
            float a0 = sadd[col], a1 = sadd[col + 1];
            int r0 = wrow + (lane >> 2), r1 = r0 + 8;
            float f0 = fmaxf(fmaf(acc[t][0], m0, a0), 0.f);
            float f1 = fmaxf(fmaf(acc[t][1], m1, a1), 0.f);
            float f2 = fmaxf(fmaf(acc[t][2], m0, a0), 0.f);
            float f3 = fmaxf(fmaf(acc[t][3], m1, a1), 0.f);
            float h0 = bf_hi(f0), h1 = bf_hi(f1), h2 = bf_hi(f2), h3 = bf_hi(f3);
            *(uint32_t*)(smem + zcur + r0 * 272 + col * 2)      = pack_bf2(f0, f1);
            *(uint32_t*)(smem + zcur + GZ + r0 * 272 + col * 2) = pack_bf2(f0 - h0, f1 - h1);
            *(uint32_t*)(smem + zcur + r1 * 272 + col * 2)      = pack_bf2(f2, f3);
            *(uint32_t*)(smem + zcur + GZ + r1 * 272 + col * 2) = pack_bf2(f2 - h2, f3 - h3);
        }
        __syncthreads();

        // ---- phase 2 ----
#pragma unroll
        for (int t = 0; t < 8; t++)
#pragma unroll
            for (int j = 0; j < 4; j++) acc[t][j] = 0.f;
        do_phase<8>(sb, zcur, wrow, whalf, lane, OFF_W2H, OFF_W2L, acc);
        __syncthreads();

        // ---- epilogue 2: bias + ReLU -> fp32 staging in Z[cur] (528 B stride) ----
#pragma unroll
        for (int t = 0; t < 8; t++) {
            int col = whalf * 64 + 8 * t + 2 * (lane & 3);
            float bb0 = sb2[col], bb1 = sb2[col + 1];
            int r0 = wrow + (lane >> 2), r1 = r0 + 8;
            float2 v0 = make_float2(fmaxf(acc[t][0] + bb0, 0.f), fmaxf(acc[t][1] + bb1, 0.f));
            float2 v1 = make_float2(fmaxf(acc[t][2] + bb0, 0.f), fmaxf(acc[t][3] + bb1, 0.f));
            *(float2*)(smem + zcur + r0 * 528 + col * 4) = v0;
            *(float2*)(smem + zcur + r1 * 528 + col * 4) = v1;
        }

        // ---- stash next tile's A into Z[nxt] ----
        if (tn < TIL) split_to_z<NF4>(smem, znxt, arow, aq, pre);
        __syncthreads();

        // ---- global write from staging ----
        {
            int c4 = tid & 31;        // 16B chunk
            int rg = (tid >> 5) * 8;  // 8 rows per thread
            if (MODE == 0) {
#pragma unroll
                for (int rr = 0; rr < 8; rr++) {
                    int row = rg + rr;
                    size_t node = base + row;
                    float4 v = *(float4*)(smem + zcur + row * 528 + c4 * 16);
                    *(float4*)(h_next + node * 128 + c4 * 4) = v;
                    *(float4*)(scr_next + node * 128 + c4 * 4) = v;
                }
            } else {
                int prev = -1;
                float4 sum = make_float4(0.f, 0.f, 0.f, 0.f);
#pragma unroll
                for (int rr = 0; rr < 8; rr++) {
                    int row = rg + rr;
                    size_t node = base + row;
                    float4 v = *(float4*)(smem + zcur + row * 528 + c4 * 16);
                    int bg = __ldg(&batch[node]);
                    if (bg == prev) {
                        sum.x += v.x; sum.y += v.y; sum.z += v.z; sum.w += v.w;
                    } else {
                        if (prev >= 0)
                            atomicAdd((float4*)(g_hg + (size_t)prev * 128 + c4 * 4), sum);
                        prev = bg;
                        sum = v;
                    }
                }
                if (prev >= 0)
                    atomicAdd((float4*)(g_hg + (size_t)prev * 128 + c4 * 4), sum);
            }
        }

        tile = tn;
        uint32_t tmp = zcur; zcur = znxt; znxt = tmp;
    }
}

// ---------------- pooled MLP head ----------------
__global__ void pool_head_kernel(const float* __restrict__ lw1,
                                 const float* __restrict__ lb1,
                                 const float* __restrict__ lw2,
                                 const float* __restrict__ lb2,
                                 float* __restrict__ out) {
    extern __shared__ float psm[];
    float* Ws   = psm;
    float* hrow = psm + HD * HD;
    float* redb = hrow + HD;

    int t = threadIdx.x;
    for (int i = t; i < HD * HD / 4; i += 128)
        ((float4*)Ws)[i] = __ldg(((const float4*)lw1) + i);
    float lb1t = __ldg(&lb1[t]);
    float w2t  = __ldg(&lw2[t]);
    float lb2v = __ldg(&lb2[0]);
    __syncthreads();

    int gbase = blockIdx.x * 8;
    for (int gi = 0; gi < 8; gi++) {
        int g = gbase + gi;
        hrow[t] = g_hg[(size_t)g * HD + t];
        __syncthreads();
        float a = 0.f;
#pragma unroll
        for (int k = 0; k < HD; k++)
            a = fmaf(hrow[k], Ws[k * HD + t], a);
        float p = fmaxf(a + lb1t, 0.f) * w2t;
#pragma unroll
        for (int o = 16; o > 0; o >>= 1)
            p += __shfl_xor_sync(0xffffffffu, p, o);
        if ((t & 31) == 0) redb[t >> 5] = p;
        __syncthreads();
        if (t == 0)
            out[g] = redb[0] + redb[1] + redb[2] + redb[3] + lb2v;
        __syncthreads();
    }
}

// ---------------- launch ----------------
extern "C" void kernel_launch(void* const* d_in, const int* in_sizes, int n_in,
                              void* d_out, int out_size) {
    const float* x   = (const float*)d_in[0];
    const int* ei    = (const int*)d_in[1];
    const int* batch = (const int*)d_in[2];
    const float* W1a = (const float*)d_in[3];
    const float* b1a = (const float*)d_in[4];
    const float* ga  = (const float*)d_in[5];
    const float* bea = (const float*)d_in[6];
    const float* rma = (const float*)d_in[7];
    const float* rva = (const float*)d_in[8];
    const float* W2a = (const float*)d_in[9];
    const float* b2a = (const float*)d_in[10];
    const float* W1b = (const float*)d_in[11];
    const float* b1b = (const float*)d_in[12];
    const float* gb  = (const float*)d_in[13];
    const float* beb = (const float*)d_in[14];
    const float* rmb = (const float*)d_in[15];
    const float* rvb = (const float*)d_in[16];
    const float* W2b = (const float*)d_in[17];
    const float* b2b = (const float*)d_in[18];
    const float* W1c = (const float*)d_in[19];
    const float* b1c = (const float*)d_in[20];
    const float* gc  = (const float*)d_in[21];
    const float* bec = (const float*)d_in[22];
    const float* rmc = (const float*)d_in[23];
    const float* rvc = (const float*)d_in[24];
    const float* W2c = (const float*)d_in[25];
    const float* b2c = (const float*)d_in[26];
    const float* lw1 = (const float*)d_in[27];
    const float* lb1 = (const float*)d_in[28];
    const float* lw2 = (const float*)d_in[29];
    const float* lb2 = (const float*)d_in[30];
    float* out = (float*)d_out;

    float *scr_a, *h1, *scr_b, *h2, *scr_c;
    cudaGetSymbolAddress((void**)&scr_a, g_scr_a);
    cudaGetSymbolAddress((void**)&h1,    g_h1);
    cudaGetSymbolAddress((void**)&scr_b, g_scr_b);
    cudaGetSymbolAddress((void**)&h2,    g_h2);
    cudaGetSymbolAddress((void**)&scr_c, g_scr_c);

    __nv_bfloat16 *Wa1, *Wa2, *Wb1, *Wb2, *Wc1, *Wc2;
    cudaGetSymbolAddress((void**)&Wa1, g_W1a);
    cudaGetSymbolAddress((void**)&Wa2, g_W2a);
    cudaGetSymbolAddress((void**)&Wb1, g_W1b);
    cudaGetSymbolAddress((void**)&Wb2, g_W2b);
    cudaGetSymbolAddress((void**)&Wc1, g_W1c);
    cudaGetSymbolAddress((void**)&Wc2, g_W2c);

    const int smem_p = (HD * HD + HD + 4) * 4;

    cudaFuncSetAttribute(gin_mma_kernel<32, 0>,
                         cudaFuncAttributeMaxDynamicSharedMemorySize, SMEM_TOTAL);
    cudaFuncSetAttribute(gin_mma_kernel<128, 0>,
                         cudaFuncAttributeMaxDynamicSharedMemorySize, SMEM_TOTAL);
    cudaFuncSetAttribute(gin_mma_kernel<128, 1>,
                         cudaFuncAttributeMaxDynamicSharedMemorySize, SMEM_TOTAL);
    cudaFuncSetAttribute(pool_head_kernel,
                         cudaFuncAttributeMaxDynamicSharedMemorySize, smem_p);

    // 1. init + weight conversion
    init_kernel<<<7500, 256>>>(x);
    setup_kernel<<<6, 256>>>(W1a, W2a, W1b, W2b, W1c, W2c);

    // 2. scatter x into scr_a
    scatter_kernel<FIN><<<18750, 256>>>(ei, x, scr_a);

    // 3. layer a (persistent)
    gin_mma_kernel<32, 0><<<GRID, 256, SMEM_TOTAL>>>(
        scr_a, Wa1, Wa1 + 128 * 32, Wa2, Wa2 + 128 * 128,
        b1a, ga, bea, rma, rva, b2a, h1, scr_b, nullptr);

    // 4. scatter h1 into scr_b
    scatter_kernel<HD><<<75000, 256>>>(ei, h1, scr_b);

    // 5. layer b
    gin_mma_kernel<128, 0><<<GRID, 256, SMEM_TOTAL>>>(
        scr_b, Wb1, Wb1 + 128 * 128, Wb2, Wb2 + 128 * 128,
        b1b, gb, beb, rmb, rvb, b2b, h2, scr_c, nullptr);

    // 6. scatter h2 into scr_c
    scatter_kernel<HD><<<75000, 256>>>(ei, h2, scr_c);

    // 7. layer c + fused pool
    gin_mma_kernel<128, 1><<<GRID, 256, SMEM_TOTAL>>>(
        scr_c, Wc1, Wc1 + 128 * 128, Wc2, Wc2 + 128 * 128,
        b1c, gc, bec, rmc, rvc, b2c, nullptr, nullptr, batch);

    // 8. head MLP
    pool_head_kernel<<<NG / 8, 128, smem_p>>>(lw1, lb1, lw2, lb2, out);
}